// round 4
// baseline (speedup 1.0000x reference)
#include <cuda_runtime.h>
#include <math.h>

// Problem dims (fixed by the dataset): B=1024, I=512, O=512. B derived at launch.
#define I_DIM 512
#define O_DIM 512

#define BM 64
#define BN 64
#define BK 32
#define PAD 33   // BK+1: conflict-free scalar LDS with stride-16 register tiling

// Scratch (allocation-free: __device__ globals)
__device__ __align__(16) float g_s2 [O_DIM * I_DIM];   // inv_covar^2 + 1e-32
__device__ __align__(16) float g_cs2[O_DIM * I_DIM];   // centers * s2
__device__ __align__(16) float g_K  [O_DIM];           // sum_i c^2 * s2

// ---------------------------------------------------------------------------
// Prep: build s2, c*s2 and the per-output constant K[o].
// One block per output row o; 256 threads stride over I.
// ---------------------------------------------------------------------------
__global__ void fgn_prep_kernel(const float* __restrict__ centers,
                                const float* __restrict__ inv_covars)
{
    int o = blockIdx.x;
    int t = threadIdx.x;
    __shared__ float red[256];

    float ksum = 0.0f;
    for (int i = t; i < I_DIM; i += 256) {
        float v  = inv_covars[o * I_DIM + i];
        float c  = centers   [o * I_DIM + i];
        float s2 = v * v + 1e-32f;
        float cs = c * s2;
        g_s2 [o * I_DIM + i] = s2;
        g_cs2[o * I_DIM + i] = cs;
        ksum += c * cs;
    }
    red[t] = ksum;
    __syncthreads();
    #pragma unroll
    for (int s = 128; s > 0; s >>= 1) {
        if (t < s) red[t] += red[t + s];
        __syncthreads();
    }
    if (t == 0) g_K[o] = red[0];
}

// ---------------------------------------------------------------------------
// Fused triple-GEMM + epilogue.
//   accL = X @ W^T            (linear part)
//   accA = X^2 @ s2^T
//   accB = X @ (c*s2)^T
//   out  = (accL + bias) * exp(-(accA - 2*accB + K))
//
// Tiling: BMxBN=64x64 per CTA, 256 threads (16x16), each thread owns a 4x4
// micro-tile with stride-16 indexing (m = ty + 16*mi, n = tx + 16*ni).
// Shared tiles stored [row][k] with PAD=33 so that:
//   - x loads broadcast across tx (2 addresses/warp)
//   - w/s2/cs2 loads hit 16 distinct banks (stride-16 n => conflict-free)
// ---------------------------------------------------------------------------
__global__ __launch_bounds__(256, 1)
void fgn_main_kernel(const float* __restrict__ X,
                     const float* __restrict__ W,
                     const float* __restrict__ bias,
                     float* __restrict__ out,
                     int B)
{
    __shared__ float Xs [BM][PAD];
    __shared__ float X2s[BM][PAD];
    __shared__ float Ws [BN][PAD];
    __shared__ float S2s[BN][PAD];
    __shared__ float Cs [BN][PAD];

    const int tid = threadIdx.x;
    const int tx  = tid & 15;   // n lane
    const int ty  = tid >> 4;   // m lane
    const int m0  = blockIdx.y * BM;
    const int n0  = blockIdx.x * BN;

    float accL[4][4] = {};
    float accA[4][4] = {};
    float accB[4][4] = {};

    for (int kt = 0; kt < I_DIM; kt += BK) {
        // ---- stage tiles: 64 rows x 32 k per matrix; 512 float4 slots,
        //      256 threads -> 2 slots each. Transposed scalar STS is
        //      conflict-free (row + 4q covers all 32 banks within a warp).
        #pragma unroll
        for (int r = 0; r < 2; r++) {
            int s   = tid + r * 256;
            int row = s >> 3;
            int q   = (s & 7) * 4;

            int gm = m0 + row; if (gm >= B) gm = B - 1;   // clamp (B always mult of 64 here)
            float4 xv = *(const float4*)&X[(size_t)gm * I_DIM + kt + q];
            Xs [row][q + 0] = xv.x;  X2s[row][q + 0] = xv.x * xv.x;
            Xs [row][q + 1] = xv.y;  X2s[row][q + 1] = xv.y * xv.y;
            Xs [row][q + 2] = xv.z;  X2s[row][q + 2] = xv.z * xv.z;
            Xs [row][q + 3] = xv.w;  X2s[row][q + 3] = xv.w * xv.w;

            int gn = n0 + row;
            float4 wv = *(const float4*)&W    [(size_t)gn * I_DIM + kt + q];
            float4 sv = *(const float4*)&g_s2 [(size_t)gn * I_DIM + kt + q];
            float4 cv = *(const float4*)&g_cs2[(size_t)gn * I_DIM + kt + q];
            Ws [row][q + 0] = wv.x;  Ws [row][q + 1] = wv.y;
            Ws [row][q + 2] = wv.z;  Ws [row][q + 3] = wv.w;
            S2s[row][q + 0] = sv.x;  S2s[row][q + 1] = sv.y;
            S2s[row][q + 2] = sv.z;  S2s[row][q + 3] = sv.w;
            Cs [row][q + 0] = cv.x;  Cs [row][q + 1] = cv.y;
            Cs [row][q + 2] = cv.z;  Cs [row][q + 3] = cv.w;
        }
        __syncthreads();

        // ---- compute: 48 FFMA + 20 LDS per thread per k (FFMA-bound)
        #pragma unroll 8
        for (int k = 0; k < BK; k++) {
            float xr[4], x2r[4], wr[4], sr[4], cr[4];
            #pragma unroll
            for (int j = 0; j < 4; j++) {
                xr [j] = Xs [ty + 16 * j][k];
                x2r[j] = X2s[ty + 16 * j][k];
                wr [j] = Ws [tx + 16 * j][k];
                sr [j] = S2s[tx + 16 * j][k];
                cr [j] = Cs [tx + 16 * j][k];
            }
            #pragma unroll
            for (int mi = 0; mi < 4; mi++) {
                #pragma unroll
                for (int ni = 0; ni < 4; ni++) {
                    accL[mi][ni] += xr [mi] * wr[ni];
                    accA[mi][ni] += x2r[mi] * sr[ni];
                    accB[mi][ni] += xr [mi] * cr[ni];
                }
            }
        }
        __syncthreads();
    }

    // ---- epilogue: out = (l + bias) * exp(-(A - 2B + K))
    #pragma unroll
    for (int mi = 0; mi < 4; mi++) {
        int m = m0 + ty + 16 * mi;
        if (m >= B) continue;
        #pragma unroll
        for (int ni = 0; ni < 4; ni++) {
            int n = n0 + tx + 16 * ni;
            float l = accL[mi][ni] + bias[n];
            float g = accA[mi][ni] - 2.0f * accB[mi][ni] + g_K[n];
            out[(size_t)m * O_DIM + n] = l * expf(-g);
        }
    }
}

// ---------------------------------------------------------------------------
// Launch. Inputs (metadata order): inputs[B,I], weights[O,I], biases[O],
// centers[O,I], inv_covars[O,I]. Output: [B,O] fp32.
// ---------------------------------------------------------------------------
extern "C" void kernel_launch(void* const* d_in, const int* in_sizes, int n_in,
                              void* d_out, int out_size)
{
    const float* X    = (const float*)d_in[0];
    const float* W    = (const float*)d_in[1];
    const float* bias = (const float*)d_in[2];
    const float* C    = (const float*)d_in[3];
    const float* V    = (const float*)d_in[4];

    const int O = in_sizes[2];               // 512
    const int I = in_sizes[1] / O;           // 512
    const int B = in_sizes[0] / I;           // 1024
    (void)I; (void)n_in; (void)out_size;

    fgn_prep_kernel<<<O, 256>>>(C, V);

    dim3 grid(O_DIM / BN, (B + BM - 1) / BM);
    fgn_main_kernel<<<grid, 256>>>(X, W, bias, (float*)d_out, B);
}